// round 6
// baseline (speedup 1.0000x reference)
#include <cuda_runtime.h>
#include <cuda_bf16.h>
#include <cstdint>

#define D 128
#define T_TYPES 4
#define MAX_N 50000
#define MAX_E 500000
#define EPS 1e-5f

// smem: only B tiles (bf16 hi/lo), 272B row stride
#define SPAD_B 272
#define OFF_BHI 0
#define OFF_BLO 34816
#define DSMEM_BYTES 69632
// final kernel C-stage aliases B region: f32, row stride 133 words (68096B <= 69632)
#define C_STRIDE 133

typedef unsigned long long u64;

// ---------------- scratch ----------------
__device__ float g_S[(size_t)T_TYPES * MAX_N * D];   // per-type summed source features
__device__ float g_acc2[(size_t)MAX_N * D];          // scattered H = relu(EF@W1+b1)
__device__ int   g_deg[T_TYPES * MAX_N];
// preconverted weights bf16 hi/lo, layout Bt[n][k] = W[k][n]
// mats: 0..3 = W_types, 4 = W_e1, 5 = W_e2, 6 = W_self
__device__ __nv_bfloat16 g_Whi[7][128 * 128];
__device__ __nv_bfloat16 g_Wlo[7][128 * 128];

// ---------------- helpers ----------------
__device__ __forceinline__ void red_add_v4(float* addr, float4 v) {
    asm volatile("red.global.add.v4.f32 [%0], {%1, %2, %3, %4};"
                 :: "l"(addr), "f"(v.x), "f"(v.y), "f"(v.z), "f"(v.w) : "memory");
}
__device__ __forceinline__ void red_add_v2(float* addr, float a, float b) {
    asm volatile("red.global.add.v2.f32 [%0], {%1, %2};"
                 :: "l"(addr), "f"(a), "f"(b) : "memory");
}
__device__ __forceinline__ uint32_t smem_u32(const void* p) {
    uint32_t a;
    asm("{ .reg .u64 t; cvta.to.shared.u64 t, %1; cvt.u32.u64 %0, t; }" : "=r"(a) : "l"(p));
    return a;
}
__device__ __forceinline__ void ldsm4(uint32_t* r, uint32_t addr) {
    asm volatile("ldmatrix.sync.aligned.m8n8.x4.shared.b16 {%0,%1,%2,%3}, [%4];"
                 : "=r"(r[0]), "=r"(r[1]), "=r"(r[2]), "=r"(r[3]) : "r"(addr));
}
__device__ __forceinline__ void mma16816(float* c, const uint32_t* a, const uint32_t* b) {
    asm volatile("mma.sync.aligned.m16n8k16.row.col.f32.bf16.bf16.f32 "
                 "{%0,%1,%2,%3}, {%4,%5,%6,%7}, {%8,%9}, {%0,%1,%2,%3};"
                 : "+f"(c[0]), "+f"(c[1]), "+f"(c[2]), "+f"(c[3])
                 : "r"(a[0]), "r"(a[1]), "r"(a[2]), "r"(a[3]), "r"(b[0]), "r"(b[1]));
}
__device__ __forceinline__ void cvt_hilo(float x, float y, uint32_t& hi, uint32_t& lo) {
    __nv_bfloat16 hx = __float2bfloat16(x), hy = __float2bfloat16(y);
    __nv_bfloat16 lx = __float2bfloat16(x - __bfloat162float(hx));
    __nv_bfloat16 ly = __float2bfloat16(y - __bfloat162float(hy));
    hi = (uint32_t)__bfloat16_as_ushort(hx) | ((uint32_t)__bfloat16_as_ushort(hy) << 16);
    lo = (uint32_t)__bfloat16_as_ushort(lx) | ((uint32_t)__bfloat16_as_ushort(ly) << 16);
}

// copy preconverted B tile ([n][k] bf16) into padded smem
__device__ __forceinline__ void copy_B(const __nv_bfloat16* ghi, const __nv_bfloat16* glo,
                                       char* dsm, int tid) {
    const uint4* sh = reinterpret_cast<const uint4*>(ghi);
    const uint4* sl = reinterpret_cast<const uint4*>(glo);
    #pragma unroll 4
    for (int it = 0; it < 8; it++) {
        int idx = it * 256 + tid;           // 2048 uint4 chunks
        int row = idx >> 4;
        int cb = (idx & 15) * 16;
        *reinterpret_cast<uint4*>(dsm + OFF_BHI + row * SPAD_B + cb) = sh[idx];
        *reinterpret_cast<uint4*>(dsm + OFF_BLO + row * SPAD_B + cb) = sl[idx];
    }
}

// warp GEMM, A from GLOBAL (row-major f32, stride D) converted in regs.
// C[tile] += A * Bt^T, split-bf16 3-product, K=128, warp tile m32 x n64.
// gr_base = global row of this warp's m-tile start; rows >= limit read as 0.
__device__ __forceinline__ void warp_gemm_regA(const float* __restrict__ srcA,
                                               int gr_base, int limit,
                                               uint32_t sb, int lane, int n0w,
                                               float acc[2][8][4]) {
    int r_in = lane >> 2;
    int c0 = (lane & 3) * 2;
    uint32_t boff = (uint32_t)((n0w + (lane & 7) + ((lane >> 3) & 2) * 4) * SPAD_B
                               + ((lane >> 3) & 1) * 16);
    uint32_t Bhi = sb + OFF_BHI + boff, Blo = sb + OFF_BLO + boff;
    #pragma unroll
    for (int ks = 0; ks < 8; ks++) {
        uint32_t k2 = (uint32_t)ks * 32;
        uint32_t bh[4][4], bl[4][4];
        #pragma unroll
        for (int q = 0; q < 4; q++) {
            ldsm4(bh[q], Bhi + q * (16 * SPAD_B) + k2);
            ldsm4(bl[q], Blo + q * (16 * SPAD_B) + k2);
        }
        #pragma unroll
        for (int mt = 0; mt < 2; mt++) {
            int ra = gr_base + mt * 16 + r_in;
            int rb = ra + 8;
            int col = ks * 16 + c0;
            const float* pa = srcA + (size_t)ra * D + col;
            const float* pb = srcA + (size_t)rb * D + col;
            float2 z2 = make_float2(0.f, 0.f);
            float2 v00 = (ra < limit) ? *reinterpret_cast<const float2*>(pa)     : z2;
            float2 v01 = (ra < limit) ? *reinterpret_cast<const float2*>(pa + 8) : z2;
            float2 v10 = (rb < limit) ? *reinterpret_cast<const float2*>(pb)     : z2;
            float2 v11 = (rb < limit) ? *reinterpret_cast<const float2*>(pb + 8) : z2;
            uint32_t ah[4], al[4];
            cvt_hilo(v00.x, v00.y, ah[0], al[0]);
            cvt_hilo(v10.x, v10.y, ah[1], al[1]);
            cvt_hilo(v01.x, v01.y, ah[2], al[2]);
            cvt_hilo(v11.x, v11.y, ah[3], al[3]);
            #pragma unroll
            for (int q = 0; q < 4; q++) {
                mma16816(acc[mt][q * 2],     ah, bh[q]);
                mma16816(acc[mt][q * 2],     ah, bl[q]);
                mma16816(acc[mt][q * 2],     al, bh[q]);
                mma16816(acc[mt][q * 2 + 1], ah, bh[q] + 2);
                mma16816(acc[mt][q * 2 + 1], ah, bl[q] + 2);
                mma16816(acc[mt][q * 2 + 1], al, bh[q] + 2);
            }
        }
    }
}

// ---------------- zero scratch ----------------
__global__ void zero_kernel(int n) {
    size_t idx = (size_t)blockIdx.x * blockDim.x + threadIdx.x;
    size_t stride = (size_t)gridDim.x * blockDim.x;
    float4 z = make_float4(0.f, 0.f, 0.f, 0.f);
    size_t nS = (size_t)T_TYPES * n * D / 4;
    for (size_t i = idx; i < nS; i += stride) reinterpret_cast<float4*>(g_S)[i] = z;
    size_t n2 = (size_t)n * D / 4;
    for (size_t i = idx; i < n2; i += stride) reinterpret_cast<float4*>(g_acc2)[i] = z;
    size_t nd = (size_t)T_TYPES * n;
    for (size_t i = idx; i < nd; i += stride) g_deg[i] = 0;
}

// ---------------- prep: weights -> bf16 hi/lo, Bt[n][k] = W[k][n] ----------------
__global__ void prep_kernel(const float* __restrict__ Wt, const float* __restrict__ W1,
                            const float* __restrict__ W2, const float* __restrict__ Ws) {
    int id = blockIdx.x * blockDim.x + threadIdx.x;
    if (id >= 7 * 128 * 128) return;
    int m = id >> 14;
    int e = id & 16383;
    int nrow = e >> 7;
    int k = e & 127;
    const float* W = (m < 4) ? (Wt + (size_t)m * 128 * 128)
                             : ((m == 4) ? W1 : ((m == 5) ? W2 : Ws));
    float v = W[k * 128 + nrow];
    __nv_bfloat16 hi = __float2bfloat16(v);
    __nv_bfloat16 lo = __float2bfloat16(v - __bfloat162float(hi));
    g_Whi[m][nrow * 128 + k] = hi;
    g_Wlo[m][nrow * 128 + k] = lo;
}

// ---------------- edge kernel: H=relu(EF@W1+b1) scatter; x gather->S_t scatter ----------------
__global__ void __launch_bounds__(256, 2) edge_kernel(const float* __restrict__ x,
                                                      const float* __restrict__ ef,
                                                      const float* __restrict__ b1,
                                                      const int* __restrict__ erow,
                                                      const int* __restrict__ ecol,
                                                      const int* __restrict__ etype,
                                                      int E, int n) {
    extern __shared__ char dsm[];
    __shared__ float s_b1[128];
    __shared__ int s_r[128], s_c[128], s_t[128];

    int tid = threadIdx.x, lane = tid & 31, wid = tid >> 5;
    int m0 = blockIdx.x * 128;
    uint32_t sb = smem_u32(dsm);

    if (tid < 128) {
        s_b1[tid] = b1[tid];
        int e = m0 + tid;
        if (e < E) {
            int r = erow[e], t = etype[e];
            s_r[tid] = r; s_c[tid] = ecol[e]; s_t[tid] = t;
            atomicAdd(&g_deg[(size_t)t * n + r], 1);
        }
    }
    copy_B(g_Whi[4], g_Wlo[4], dsm, tid);
    __syncthreads();

    float acc[2][8][4];
    #pragma unroll
    for (int mt = 0; mt < 2; mt++)
        #pragma unroll
        for (int nt = 0; nt < 8; nt++)
            #pragma unroll
            for (int j = 0; j < 4; j++) acc[mt][nt][j] = 0.f;

    int m0w = (wid >> 1) * 32, n0w = (wid & 1) * 64;
    warp_gemm_regA(ef, m0 + m0w, E, sb, lane, n0w, acc);

    // H epilogue: relu + bias -> red into g_acc2[row]
    #pragma unroll
    for (int mt = 0; mt < 2; mt++) {
        int er0 = m0w + mt * 16 + (lane >> 2);
        int er1 = er0 + 8;
        bool v0 = (m0 + er0) < E, v1 = (m0 + er1) < E;
        int r0 = v0 ? s_r[er0] : 0, r1 = v1 ? s_r[er1] : 0;
        #pragma unroll
        for (int nt = 0; nt < 8; nt++) {
            int cj = n0w + nt * 8 + (lane & 3) * 2;
            float bb0 = s_b1[cj], bb1 = s_b1[cj + 1];
            if (v0) {
                float h0 = fmaxf(acc[mt][nt][0] + bb0, 0.f);
                float h1 = fmaxf(acc[mt][nt][1] + bb1, 0.f);
                red_add_v2(g_acc2 + (size_t)r0 * D + cj, h0, h1);
            }
            if (v1) {
                float h2 = fmaxf(acc[mt][nt][2] + bb0, 0.f);
                float h3 = fmaxf(acc[mt][nt][3] + bb1, 0.f);
                red_add_v2(g_acc2 + (size_t)r1 * D + cj, h2, h3);
            }
        }
    }

    // x gather -> S_t scatter (2 threads per edge)
    {
        int el = tid >> 1;
        int half = (tid & 1) * 64;
        int e = m0 + el;
        if (e < E) {
            int r = s_r[el], cn = s_c[el], t = s_t[el];
            const float4* xs = reinterpret_cast<const float4*>(x + (size_t)cn * D + half);
            float* dst = g_S + ((size_t)t * n + r) * D + half;
            #pragma unroll
            for (int j = 0; j < 16; j++) red_add_v4(dst + 4 * j, xs[j]);
        }
    }
}

// ---------------- final: out = relu(LN(sum_t S_t@W_t + acc2@W2 + x@Wself + biases)) ------------
__global__ void __launch_bounds__(256, 2) final_kernel(const float* __restrict__ x,
                                                       const float* __restrict__ bself,
                                                       const float* __restrict__ btypes,
                                                       const float* __restrict__ be2,
                                                       const float* __restrict__ lng,
                                                       const float* __restrict__ lnb,
                                                       float* __restrict__ out,
                                                       int n) {
    extern __shared__ char dsm[];
    __shared__ float s_bself[128], s_be2[128], s_g[128], s_lb[128];
    __shared__ float s_bt[T_TYPES][128];

    int tid = threadIdx.x, lane = tid & 31, wid = tid >> 5;
    int m0 = blockIdx.x * 128;
    uint32_t sb = smem_u32(dsm);

    if (tid < 128) {
        s_bself[tid] = bself[tid];
        s_be2[tid] = be2[tid];
        s_g[tid] = lng[tid];
        s_lb[tid] = lnb[tid];
        #pragma unroll
        for (int t = 0; t < T_TYPES; t++) s_bt[t][tid] = btypes[t * D + tid];
    }

    float acc[2][8][4];
    #pragma unroll
    for (int mt = 0; mt < 2; mt++)
        #pragma unroll
        for (int nt = 0; nt < 8; nt++)
            #pragma unroll
            for (int j = 0; j < 4; j++) acc[mt][nt][j] = 0.f;

    int m0w = (wid >> 1) * 32, n0w = (wid & 1) * 64;

    #pragma unroll 1
    for (int ph = 0; ph < 6; ph++) {
        const float* srcA;
        int mat;
        if (ph < 4)      { srcA = g_S + (size_t)ph * n * D; mat = ph; }
        else if (ph == 4){ srcA = g_acc2;                   mat = 5;  }
        else             { srcA = x;                        mat = 6;  }
        __syncthreads();
        copy_B(g_Whi[mat], g_Wlo[mat], dsm, tid);
        __syncthreads();
        warp_gemm_regA(srcA, m0 + m0w, n, sb, lane, n0w, acc);
    }
    __syncthreads();   // all smem B reads done; safe to alias C over B region

    // stage C into smem f32 [128][C_STRIDE]
    float* Cs = reinterpret_cast<float*>(dsm);
    #pragma unroll
    for (int mt = 0; mt < 2; mt++) {
        int er0 = m0w + mt * 16 + (lane >> 2);
        #pragma unroll
        for (int nt = 0; nt < 8; nt++) {
            int cj = n0w + nt * 8 + (lane & 3) * 2;
            Cs[er0 * C_STRIDE + cj]       = acc[mt][nt][0];
            Cs[er0 * C_STRIDE + cj + 1]   = acc[mt][nt][1];
            Cs[(er0 + 8) * C_STRIDE + cj]     = acc[mt][nt][2];
            Cs[(er0 + 8) * C_STRIDE + cj + 1] = acc[mt][nt][3];
        }
    }
    __syncthreads();

    // per-row LN (threads 0..127)
    if (tid < 128) {
        int gm = m0 + tid;
        if (gm < n) {
            int d0 = g_deg[0 * (size_t)n + gm];
            int d1 = g_deg[1 * (size_t)n + gm];
            int d2 = g_deg[2 * (size_t)n + gm];
            int d3 = g_deg[3 * (size_t)n + gm];
            float f0 = (float)d0, f1 = (float)d1, f2 = (float)d2, f3 = (float)d3;
            float degs = f0 + f1 + f2 + f3;
            float* row = Cs + tid * C_STRIDE;
            float s = 0.f, sq = 0.f;
            #pragma unroll 8
            for (int j = 0; j < 128; j++) {
                float val = row[j] + s_bself[j]
                          + f0 * s_bt[0][j] + f1 * s_bt[1][j]
                          + f2 * s_bt[2][j] + f3 * s_bt[3][j]
                          + degs * s_be2[j];
                row[j] = val;
                s += val; sq += val * val;
            }
            float mu = s * (1.f / 128.f);
            float var = sq * (1.f / 128.f) - mu * mu;
            float inv = rsqrtf(fmaxf(var, 0.f) + EPS);
            float* op = out + (size_t)gm * D;
            #pragma unroll 8
            for (int j = 0; j < 32; j++) {
                float4 o;
                o.x = fmaxf((row[4*j+0] - mu) * inv * s_g[4*j+0] + s_lb[4*j+0], 0.f);
                o.y = fmaxf((row[4*j+1] - mu) * inv * s_g[4*j+1] + s_lb[4*j+1], 0.f);
                o.z = fmaxf((row[4*j+2] - mu) * inv * s_g[4*j+2] + s_lb[4*j+2], 0.f);
                o.w = fmaxf((row[4*j+3] - mu) * inv * s_g[4*j+3] + s_lb[4*j+3], 0.f);
                *reinterpret_cast<float4*>(op + 4 * j) = o;
            }
        }
    }
}

// ---------------- launch ----------------
extern "C" void kernel_launch(void* const* d_in, const int* in_sizes, int n_in,
                              void* d_out, int out_size) {
    const float* x    = (const float*)d_in[0];
    const int*   ei   = (const int*)d_in[1];
    const int*   etyp = (const int*)d_in[2];
    const float* ef   = (const float*)d_in[3];
    const float* Wt   = (const float*)d_in[4];
    const float* bt   = (const float*)d_in[5];
    const float* Ws   = (const float*)d_in[6];
    const float* bs   = (const float*)d_in[7];
    const float* W1   = (const float*)d_in[8];
    const float* b1   = (const float*)d_in[9];
    const float* W2   = (const float*)d_in[10];
    const float* b2   = (const float*)d_in[11];
    const float* lg   = (const float*)d_in[12];
    const float* lb   = (const float*)d_in[13];
    float* out = (float*)d_out;

    int E = in_sizes[2];
    int n = in_sizes[0] / D;
    const int* erow = ei;       // destinations (segment ids)
    const int* ecol = ei + E;   // sources (gather ids)

    cudaFuncSetAttribute(edge_kernel, cudaFuncAttributeMaxDynamicSharedMemorySize, DSMEM_BYTES);
    cudaFuncSetAttribute(final_kernel, cudaFuncAttributeMaxDynamicSharedMemorySize, DSMEM_BYTES);

    zero_kernel<<<1024, 256>>>(n);
    prep_kernel<<<(7 * 128 * 128 + 255) / 256, 256>>>(Wt, W1, W2, Ws);
    edge_kernel<<<(E + 127) / 128, 256, DSMEM_BYTES>>>(x, ef, b1, erow, ecol, etyp, E, n);
    final_kernel<<<(n + 127) / 128, 256, DSMEM_BYTES>>>(x, bs, bt, b2, lg, lb, out, n);
}

// round 9
// speedup vs baseline: 1.3119x; 1.3119x over previous
#include <cuda_runtime.h>
#include <cuda_bf16.h>
#include <cstdint>

#define D 128
#define T_TYPES 4
#define MAX_N 50000
#define MAX_E 500000
#define EPS 1e-5f

// smem: only B tiles (bf16 hi/lo), 272B row stride
#define SPAD_B 272
#define OFF_BHI 0
#define OFF_BLO 34816
#define DSMEM_BYTES 69632
// final kernel C-stage aliases B region: f32, row stride 133 words (68096B <= 69632)
#define C_STRIDE 133

typedef unsigned long long u64;

// ---------------- scratch ----------------
__device__ float g_S[(size_t)T_TYPES * MAX_N * D];   // per-type summed source features
__device__ float g_acc2[(size_t)MAX_N * D];          // scattered H = relu(EF@W1+b1)
__device__ int   g_deg[T_TYPES * MAX_N];
// preconverted weights bf16 hi/lo, layout Bt[n][k] = W[k][n]
// mats: 0..3 = W_types, 4 = W_e1, 5 = W_e2, 6 = W_self
__device__ __nv_bfloat16 g_Whi[7][128 * 128];
__device__ __nv_bfloat16 g_Wlo[7][128 * 128];

// ---------------- helpers ----------------
__device__ __forceinline__ void red_add_v4(float* addr, float4 v) {
    asm volatile("red.global.add.v4.f32 [%0], {%1, %2, %3, %4};"
                 :: "l"(addr), "f"(v.x), "f"(v.y), "f"(v.z), "f"(v.w) : "memory");
}
__device__ __forceinline__ void red_add_v2(float* addr, float a, float b) {
    asm volatile("red.global.add.v2.f32 [%0], {%1, %2};"
                 :: "l"(addr), "f"(a), "f"(b) : "memory");
}
__device__ __forceinline__ uint32_t smem_u32(const void* p) {
    uint32_t a;
    asm("{ .reg .u64 t; cvta.to.shared.u64 t, %1; cvt.u32.u64 %0, t; }" : "=r"(a) : "l"(p));
    return a;
}
__device__ __forceinline__ void ldsm4(uint32_t* r, uint32_t addr) {
    asm volatile("ldmatrix.sync.aligned.m8n8.x4.shared.b16 {%0,%1,%2,%3}, [%4];"
                 : "=r"(r[0]), "=r"(r[1]), "=r"(r[2]), "=r"(r[3]) : "r"(addr));
}
__device__ __forceinline__ void mma16816(float* c, const uint32_t* a, const uint32_t* b) {
    asm volatile("mma.sync.aligned.m16n8k16.row.col.f32.bf16.bf16.f32 "
                 "{%0,%1,%2,%3}, {%4,%5,%6,%7}, {%8,%9}, {%0,%1,%2,%3};"
                 : "+f"(c[0]), "+f"(c[1]), "+f"(c[2]), "+f"(c[3])
                 : "r"(a[0]), "r"(a[1]), "r"(a[2]), "r"(a[3]), "r"(b[0]), "r"(b[1]));
}
__device__ __forceinline__ void cvt_hilo(float x, float y, uint32_t& hi, uint32_t& lo) {
    __nv_bfloat16 hx = __float2bfloat16(x), hy = __float2bfloat16(y);
    __nv_bfloat16 lx = __float2bfloat16(x - __bfloat162float(hx));
    __nv_bfloat16 ly = __float2bfloat16(y - __bfloat162float(hy));
    hi = (uint32_t)__bfloat16_as_ushort(hx) | ((uint32_t)__bfloat16_as_ushort(hy) << 16);
    lo = (uint32_t)__bfloat16_as_ushort(lx) | ((uint32_t)__bfloat16_as_ushort(ly) << 16);
}

// copy preconverted B tile ([n][k] bf16) into padded smem
__device__ __forceinline__ void copy_B(const __nv_bfloat16* ghi, const __nv_bfloat16* glo,
                                       char* dsm, int tid) {
    const uint4* sh = reinterpret_cast<const uint4*>(ghi);
    const uint4* sl = reinterpret_cast<const uint4*>(glo);
    #pragma unroll 4
    for (int it = 0; it < 8; it++) {
        int idx = it * 256 + tid;           // 2048 uint4 chunks
        int row = idx >> 4;
        int cb = (idx & 15) * 16;
        *reinterpret_cast<uint4*>(dsm + OFF_BHI + row * SPAD_B + cb) = sh[idx];
        *reinterpret_cast<uint4*>(dsm + OFF_BLO + row * SPAD_B + cb) = sl[idx];
    }
}

// load one A fragment pair (4 x float2) for (ks, mt)
__device__ __forceinline__ void loadA_pair(const float* __restrict__ srcA, int gr_base,
                                           int limit, int r_in, int c0, int ks, int mt,
                                           float2 v[4]) {
    int ra = gr_base + mt * 16 + r_in;
    int rb = ra + 8;
    int col = ks * 16 + c0;
    const float* pa = srcA + (size_t)ra * D + col;
    const float* pb = srcA + (size_t)rb * D + col;
    float2 z2 = make_float2(0.f, 0.f);
    v[0] = (ra < limit) ? *reinterpret_cast<const float2*>(pa)     : z2;
    v[1] = (ra < limit) ? *reinterpret_cast<const float2*>(pa + 8) : z2;
    v[2] = (rb < limit) ? *reinterpret_cast<const float2*>(pb)     : z2;
    v[3] = (rb < limit) ? *reinterpret_cast<const float2*>(pb + 8) : z2;
}

// warp GEMM, A from GLOBAL with one-fragment-ahead register prefetch.
// C[tile] += A * Bt^T, split-bf16 3-product, K=128, warp tile m32 x n64.
__device__ __forceinline__ void warp_gemm_regA(const float* __restrict__ srcA,
                                               int gr_base, int limit,
                                               uint32_t sb, int lane, int n0w,
                                               float acc[2][8][4]) {
    int r_in = lane >> 2;
    int c0 = (lane & 3) * 2;
    uint32_t boff = (uint32_t)((n0w + (lane & 7) + ((lane >> 3) & 2) * 4) * SPAD_B
                               + ((lane >> 3) & 1) * 16);
    uint32_t Bhi = sb + OFF_BHI + boff, Blo = sb + OFF_BLO + boff;

    float2 cur[4], nxt[4];
    loadA_pair(srcA, gr_base, limit, r_in, c0, 0, 0, cur);

    #pragma unroll
    for (int ks = 0; ks < 8; ks++) {
        uint32_t k2 = (uint32_t)ks * 32;
        #pragma unroll
        for (int mt = 0; mt < 2; mt++) {
            // prefetch next fragment while this one's MMAs run
            if (!(ks == 7 && mt == 1)) {
                int nks = (mt == 0) ? ks : ks + 1;
                loadA_pair(srcA, gr_base, limit, r_in, c0, nks, mt ^ 1, nxt);
            }
            uint32_t ah[4], al[4];
            cvt_hilo(cur[0].x, cur[0].y, ah[0], al[0]);
            cvt_hilo(cur[2].x, cur[2].y, ah[1], al[1]);
            cvt_hilo(cur[1].x, cur[1].y, ah[2], al[2]);
            cvt_hilo(cur[3].x, cur[3].y, ah[3], al[3]);
            #pragma unroll
            for (int q = 0; q < 4; q++) {
                uint32_t bh[4], bl[4];
                ldsm4(bh, Bhi + q * (16 * SPAD_B) + k2);
                ldsm4(bl, Blo + q * (16 * SPAD_B) + k2);
                mma16816(acc[mt][q * 2],     ah, bh);
                mma16816(acc[mt][q * 2],     ah, bl);
                mma16816(acc[mt][q * 2],     al, bh);
                mma16816(acc[mt][q * 2 + 1], ah, bh + 2);
                mma16816(acc[mt][q * 2 + 1], ah, bl + 2);
                mma16816(acc[mt][q * 2 + 1], al, bh + 2);
            }
            cur[0] = nxt[0]; cur[1] = nxt[1]; cur[2] = nxt[2]; cur[3] = nxt[3];
        }
    }
}

// ---------------- zero scratch ----------------
__global__ void zero_kernel(int n) {
    size_t idx = (size_t)blockIdx.x * blockDim.x + threadIdx.x;
    size_t stride = (size_t)gridDim.x * blockDim.x;
    float4 z = make_float4(0.f, 0.f, 0.f, 0.f);
    size_t nS = (size_t)T_TYPES * n * D / 4;
    for (size_t i = idx; i < nS; i += stride) reinterpret_cast<float4*>(g_S)[i] = z;
    size_t n2 = (size_t)n * D / 4;
    for (size_t i = idx; i < n2; i += stride) reinterpret_cast<float4*>(g_acc2)[i] = z;
    size_t nd = (size_t)T_TYPES * n;
    for (size_t i = idx; i < nd; i += stride) g_deg[i] = 0;
}

// ---------------- prep: weights -> bf16 hi/lo, Bt[n][k] = W[k][n] ----------------
__global__ void prep_kernel(const float* __restrict__ Wt, const float* __restrict__ W1,
                            const float* __restrict__ W2, const float* __restrict__ Ws) {
    int id = blockIdx.x * blockDim.x + threadIdx.x;
    if (id >= 7 * 128 * 128) return;
    int m = id >> 14;
    int e = id & 16383;
    int nrow = e >> 7;
    int k = e & 127;
    const float* W = (m < 4) ? (Wt + (size_t)m * 128 * 128)
                             : ((m == 4) ? W1 : ((m == 5) ? W2 : Ws));
    float v = W[k * 128 + nrow];
    __nv_bfloat16 hi = __float2bfloat16(v);
    __nv_bfloat16 lo = __float2bfloat16(v - __bfloat162float(hi));
    g_Whi[m][nrow * 128 + k] = hi;
    g_Wlo[m][nrow * 128 + k] = lo;
}

// ---------------- edge kernel: H=relu(EF@W1+b1) scatter; x gather->S_t scatter ----------------
__global__ void __launch_bounds__(256, 2) edge_kernel(const float* __restrict__ x,
                                                      const float* __restrict__ ef,
                                                      const float* __restrict__ b1,
                                                      const int* __restrict__ erow,
                                                      const int* __restrict__ ecol,
                                                      const int* __restrict__ etype,
                                                      int E, int n) {
    extern __shared__ char dsm[];
    __shared__ float s_b1[128];
    __shared__ int s_r[128], s_c[128], s_t[128];

    int tid = threadIdx.x, lane = tid & 31, wid = tid >> 5;
    int m0 = blockIdx.x * 128;
    uint32_t sb = smem_u32(dsm);

    if (tid < 128) {
        s_b1[tid] = b1[tid];
        int e = m0 + tid;
        if (e < E) {
            int r = erow[e], t = etype[e];
            s_r[tid] = r; s_c[tid] = ecol[e]; s_t[tid] = t;
            atomicAdd(&g_deg[(size_t)t * n + r], 1);
        }
    }
    copy_B(g_Whi[4], g_Wlo[4], dsm, tid);
    __syncthreads();

    float acc[2][8][4];
    #pragma unroll
    for (int mt = 0; mt < 2; mt++)
        #pragma unroll
        for (int nt = 0; nt < 8; nt++)
            #pragma unroll
            for (int j = 0; j < 4; j++) acc[mt][nt][j] = 0.f;

    int m0w = (wid >> 1) * 32, n0w = (wid & 1) * 64;
    warp_gemm_regA(ef, m0 + m0w, E, sb, lane, n0w, acc);

    // H epilogue: relu + bias -> red into g_acc2[row]
    #pragma unroll
    for (int mt = 0; mt < 2; mt++) {
        int er0 = m0w + mt * 16 + (lane >> 2);
        int er1 = er0 + 8;
        bool v0 = (m0 + er0) < E, v1 = (m0 + er1) < E;
        int r0 = v0 ? s_r[er0] : 0, r1 = v1 ? s_r[er1] : 0;
        #pragma unroll
        for (int nt = 0; nt < 8; nt++) {
            int cj = n0w + nt * 8 + (lane & 3) * 2;
            float bb0 = s_b1[cj], bb1 = s_b1[cj + 1];
            if (v0) {
                float h0 = fmaxf(acc[mt][nt][0] + bb0, 0.f);
                float h1 = fmaxf(acc[mt][nt][1] + bb1, 0.f);
                red_add_v2(g_acc2 + (size_t)r0 * D + cj, h0, h1);
            }
            if (v1) {
                float h2 = fmaxf(acc[mt][nt][2] + bb0, 0.f);
                float h3 = fmaxf(acc[mt][nt][3] + bb1, 0.f);
                red_add_v2(g_acc2 + (size_t)r1 * D + cj, h2, h3);
            }
        }
    }

    // x gather -> S_t scatter (2 threads per edge)
    {
        int el = tid >> 1;
        int half = (tid & 1) * 64;
        int e = m0 + el;
        if (e < E) {
            int r = s_r[el], cn = s_c[el], t = s_t[el];
            const float4* xs = reinterpret_cast<const float4*>(x + (size_t)cn * D + half);
            float* dst = g_S + ((size_t)t * n + r) * D + half;
            #pragma unroll
            for (int j = 0; j < 16; j++) red_add_v4(dst + 4 * j, xs[j]);
        }
    }
}

// ---------------- final: out = relu(LN(sum_t S_t@W_t + acc2@W2 + x@Wself + biases)) ------------
__global__ void __launch_bounds__(256, 2) final_kernel(const float* __restrict__ x,
                                                       const float* __restrict__ bself,
                                                       const float* __restrict__ btypes,
                                                       const float* __restrict__ be2,
                                                       const float* __restrict__ lng,
                                                       const float* __restrict__ lnb,
                                                       float* __restrict__ out,
                                                       int n) {
    extern __shared__ char dsm[];
    __shared__ float s_bself[128], s_be2[128], s_g[128], s_lb[128];
    __shared__ float s_bt[T_TYPES][128];

    int tid = threadIdx.x, lane = tid & 31, wid = tid >> 5;
    int m0 = blockIdx.x * 128;
    uint32_t sb = smem_u32(dsm);

    if (tid < 128) {
        s_bself[tid] = bself[tid];
        s_be2[tid] = be2[tid];
        s_g[tid] = lng[tid];
        s_lb[tid] = lnb[tid];
        #pragma unroll
        for (int t = 0; t < T_TYPES; t++) s_bt[t][tid] = btypes[t * D + tid];
    }

    float acc[2][8][4];
    #pragma unroll
    for (int mt = 0; mt < 2; mt++)
        #pragma unroll
        for (int nt = 0; nt < 8; nt++)
            #pragma unroll
            for (int j = 0; j < 4; j++) acc[mt][nt][j] = 0.f;

    int m0w = (wid >> 1) * 32, n0w = (wid & 1) * 64;

    #pragma unroll 1
    for (int ph = 0; ph < 6; ph++) {
        const float* srcA;
        int mat;
        if (ph < 4)      { srcA = g_S + (size_t)ph * n * D; mat = ph; }
        else if (ph == 4){ srcA = g_acc2;                   mat = 5;  }
        else             { srcA = x;                        mat = 6;  }
        __syncthreads();
        copy_B(g_Whi[mat], g_Wlo[mat], dsm, tid);
        __syncthreads();
        warp_gemm_regA(srcA, m0 + m0w, n, sb, lane, n0w, acc);
    }
    __syncthreads();   // all smem B reads done; safe to alias C over B region

    // stage C into smem f32 [128][C_STRIDE]
    float* Cs = reinterpret_cast<float*>(dsm);
    #pragma unroll
    for (int mt = 0; mt < 2; mt++) {
        int er0 = m0w + mt * 16 + (lane >> 2);
        #pragma unroll
        for (int nt = 0; nt < 8; nt++) {
            int cj = n0w + nt * 8 + (lane & 3) * 2;
            Cs[er0 * C_STRIDE + cj]       = acc[mt][nt][0];
            Cs[er0 * C_STRIDE + cj + 1]   = acc[mt][nt][1];
            Cs[(er0 + 8) * C_STRIDE + cj]     = acc[mt][nt][2];
            Cs[(er0 + 8) * C_STRIDE + cj + 1] = acc[mt][nt][3];
        }
    }
    __syncthreads();

    // per-row LN (threads 0..127)
    if (tid < 128) {
        int gm = m0 + tid;
        if (gm < n) {
            int d0 = g_deg[0 * (size_t)n + gm];
            int d1 = g_deg[1 * (size_t)n + gm];
            int d2 = g_deg[2 * (size_t)n + gm];
            int d3 = g_deg[3 * (size_t)n + gm];
            float f0 = (float)d0, f1 = (float)d1, f2 = (float)d2, f3 = (float)d3;
            float degs = f0 + f1 + f2 + f3;
            float* row = Cs + tid * C_STRIDE;
            float s = 0.f, sq = 0.f;
            #pragma unroll 8
            for (int j = 0; j < 128; j++) {
                float val = row[j] + s_bself[j]
                          + f0 * s_bt[0][j] + f1 * s_bt[1][j]
                          + f2 * s_bt[2][j] + f3 * s_bt[3][j]
                          + degs * s_be2[j];
                row[j] = val;
                s += val; sq += val * val;
            }
            float mu = s * (1.f / 128.f);
            float var = sq * (1.f / 128.f) - mu * mu;
            float inv = rsqrtf(fmaxf(var, 0.f) + EPS);
            float* op = out + (size_t)gm * D;
            #pragma unroll 8
            for (int j = 0; j < 32; j++) {
                float4 o;
                o.x = fmaxf((row[4*j+0] - mu) * inv * s_g[4*j+0] + s_lb[4*j+0], 0.f);
                o.y = fmaxf((row[4*j+1] - mu) * inv * s_g[4*j+1] + s_lb[4*j+1], 0.f);
                o.z = fmaxf((row[4*j+2] - mu) * inv * s_g[4*j+2] + s_lb[4*j+2], 0.f);
                o.w = fmaxf((row[4*j+3] - mu) * inv * s_g[4*j+3] + s_lb[4*j+3], 0.f);
                *reinterpret_cast<float4*>(op + 4 * j) = o;
            }
        }
    }
}

// ---------------- launch ----------------
extern "C" void kernel_launch(void* const* d_in, const int* in_sizes, int n_in,
                              void* d_out, int out_size) {
    const float* x    = (const float*)d_in[0];
    const int*   ei   = (const int*)d_in[1];
    const int*   etyp = (const int*)d_in[2];
    const float* ef   = (const float*)d_in[3];
    const float* Wt   = (const float*)d_in[4];
    const float* bt   = (const float*)d_in[5];
    const float* Ws   = (const float*)d_in[6];
    const float* bs   = (const float*)d_in[7];
    const float* W1   = (const float*)d_in[8];
    const float* b1   = (const float*)d_in[9];
    const float* W2   = (const float*)d_in[10];
    const float* b2   = (const float*)d_in[11];
    const float* lg   = (const float*)d_in[12];
    const float* lb   = (const float*)d_in[13];
    float* out = (float*)d_out;

    int E = in_sizes[2];
    int n = in_sizes[0] / D;
    const int* erow = ei;       // destinations (segment ids)
    const int* ecol = ei + E;   // sources (gather ids)

    cudaFuncSetAttribute(edge_kernel, cudaFuncAttributeMaxDynamicSharedMemorySize, DSMEM_BYTES);
    cudaFuncSetAttribute(final_kernel, cudaFuncAttributeMaxDynamicSharedMemorySize, DSMEM_BYTES);

    zero_kernel<<<1024, 256>>>(n);
    prep_kernel<<<(7 * 128 * 128 + 255) / 256, 256>>>(Wt, W1, W2, Ws);
    edge_kernel<<<(E + 127) / 128, 256, DSMEM_BYTES>>>(x, ef, b1, erow, ecol, etyp, E, n);
    final_kernel<<<(n + 127) / 128, 256, DSMEM_BYTES>>>(x, bs, bt, b2, lg, lb, out, n);
}

// round 13
// speedup vs baseline: 1.4782x; 1.1268x over previous
#include <cuda_runtime.h>
#include <cuda_bf16.h>
#include <cstdint>

#define D 128
#define T_TYPES 4
#define MAX_N 50000
#define MAX_E 500000
#define EPS 1e-5f

// smem: only B tiles (bf16 hi/lo), 272B row stride
#define SPAD_B 272
#define OFF_BHI 0
#define OFF_BLO 34816
#define DSMEM_BYTES 69632
// final kernel C-stage aliases B region: f32, row stride 133 words (68096B <= 69632)
#define C_STRIDE 133

typedef unsigned long long u64;

// ---------------- scratch ----------------
__device__ float g_S[(size_t)T_TYPES * MAX_N * D];   // per-type summed source features
__device__ float g_acc2[(size_t)MAX_N * D];          // scattered H = relu(EF@W1+b1)
__device__ int   g_deg[T_TYPES * MAX_N];
// preconverted weights bf16 hi/lo, layout Bt[n][k] = W[k][n]
// mats: 0..3 = W_types, 4 = W_e1, 5 = W_e2, 6 = W_self
__device__ __nv_bfloat16 g_Whi[7][128 * 128];
__device__ __nv_bfloat16 g_Wlo[7][128 * 128];

// ---------------- helpers ----------------
__device__ __forceinline__ void red_add_v4(float* addr, float4 v) {
    asm volatile("red.global.add.v4.f32 [%0], {%1, %2, %3, %4};"
                 :: "l"(addr), "f"(v.x), "f"(v.y), "f"(v.z), "f"(v.w) : "memory");
}
__device__ __forceinline__ void red_add_v2(float* addr, float a, float b) {
    asm volatile("red.global.add.v2.f32 [%0], {%1, %2};"
                 :: "l"(addr), "f"(a), "f"(b) : "memory");
}
__device__ __forceinline__ uint32_t smem_u32(const void* p) {
    uint32_t a;
    asm("{ .reg .u64 t; cvta.to.shared.u64 t, %1; cvt.u32.u64 %0, t; }" : "=r"(a) : "l"(p));
    return a;
}
__device__ __forceinline__ void ldsm4(uint32_t* r, uint32_t addr) {
    asm volatile("ldmatrix.sync.aligned.m8n8.x4.shared.b16 {%0,%1,%2,%3}, [%4];"
                 : "=r"(r[0]), "=r"(r[1]), "=r"(r[2]), "=r"(r[3]) : "r"(addr));
}
__device__ __forceinline__ void mma16816(float* c, const uint32_t* a, const uint32_t* b) {
    asm volatile("mma.sync.aligned.m16n8k16.row.col.f32.bf16.bf16.f32 "
                 "{%0,%1,%2,%3}, {%4,%5,%6,%7}, {%8,%9}, {%0,%1,%2,%3};"
                 : "+f"(c[0]), "+f"(c[1]), "+f"(c[2]), "+f"(c[3])
                 : "r"(a[0]), "r"(a[1]), "r"(a[2]), "r"(a[3]), "r"(b[0]), "r"(b[1]));
}
// truncation-based hi/lo split for a pair of floats -> two bf16x2 words.
// hi = top 16 bits of each float (PRMT); rem = x - hi (exact); lo = top 16 of rem.
__device__ __forceinline__ void cvt_hilo2(float x, float y, uint32_t& hi, uint32_t& lo) {
    uint32_t ux = __float_as_uint(x), uy = __float_as_uint(y);
    hi = __byte_perm(ux, uy, 0x7632);
    float rx = x - __uint_as_float(ux & 0xFFFF0000u);
    float ry = y - __uint_as_float(uy & 0xFFFF0000u);
    lo = __byte_perm(__float_as_uint(rx), __float_as_uint(ry), 0x7632);
}
// convert one A fragment (4 x float2) into mma-ordered bf16x2 regs
__device__ __forceinline__ void cvt_frag(const float2 v[4], uint32_t ah[4], uint32_t al[4]) {
    cvt_hilo2(v[0].x, v[0].y, ah[0], al[0]);
    cvt_hilo2(v[2].x, v[2].y, ah[1], al[1]);
    cvt_hilo2(v[1].x, v[1].y, ah[2], al[2]);
    cvt_hilo2(v[3].x, v[3].y, ah[3], al[3]);
}

// copy preconverted B tile ([n][k] bf16) into padded smem
__device__ __forceinline__ void copy_B(const __nv_bfloat16* ghi, const __nv_bfloat16* glo,
                                       char* dsm, int tid) {
    const uint4* sh = reinterpret_cast<const uint4*>(ghi);
    const uint4* sl = reinterpret_cast<const uint4*>(glo);
    #pragma unroll 4
    for (int it = 0; it < 8; it++) {
        int idx = it * 256 + tid;           // 2048 uint4 chunks
        int row = idx >> 4;
        int cb = (idx & 15) * 16;
        *reinterpret_cast<uint4*>(dsm + OFF_BHI + row * SPAD_B + cb) = sh[idx];
        *reinterpret_cast<uint4*>(dsm + OFF_BLO + row * SPAD_B + cb) = sl[idx];
    }
}

// load one A fragment pair (4 x float2) for (ks, mt)
__device__ __forceinline__ void loadA_pair(const float* __restrict__ srcA, int gr_base,
                                           int limit, int r_in, int c0, int ks, int mt,
                                           float2 v[4]) {
    int ra = gr_base + mt * 16 + r_in;
    int rb = ra + 8;
    int col = ks * 16 + c0;
    const float* pa = srcA + (size_t)ra * D + col;
    const float* pb = srcA + (size_t)rb * D + col;
    float2 z2 = make_float2(0.f, 0.f);
    v[0] = (ra < limit) ? *reinterpret_cast<const float2*>(pa)     : z2;
    v[1] = (ra < limit) ? *reinterpret_cast<const float2*>(pa + 8) : z2;
    v[2] = (rb < limit) ? *reinterpret_cast<const float2*>(pb)     : z2;
    v[3] = (rb < limit) ? *reinterpret_cast<const float2*>(pb + 8) : z2;
}

// warp GEMM, A from GLOBAL with one-ks-ahead register prefetch (two buffers).
// C[tile] += A * Bt^T, split-bf16 3-product, K=128, warp tile m32 x n64.
__device__ __forceinline__ void warp_gemm_regA(const float* __restrict__ srcA,
                                               int gr_base, int limit,
                                               uint32_t sb, int lane, int n0w,
                                               float acc[2][8][4]) {
    int r_in = lane >> 2;
    int c0 = (lane & 3) * 2;
    uint32_t boff = (uint32_t)((n0w + (lane & 7) + ((lane >> 3) & 2) * 4) * SPAD_B
                               + ((lane >> 3) & 1) * 16);
    uint32_t Bhi = sb + OFF_BHI + boff, Blo = sb + OFF_BLO + boff;

    float2 bufA[4], bufB[4];
    loadA_pair(srcA, gr_base, limit, r_in, c0, 0, 0, bufA);
    loadA_pair(srcA, gr_base, limit, r_in, c0, 0, 1, bufB);

    #pragma unroll
    for (int ks = 0; ks < 8; ks++) {
        uint32_t ah[2][4], al[2][4];
        cvt_frag(bufA, ah[0], al[0]);
        if (ks < 7) loadA_pair(srcA, gr_base, limit, r_in, c0, ks + 1, 0, bufA);
        cvt_frag(bufB, ah[1], al[1]);
        if (ks < 7) loadA_pair(srcA, gr_base, limit, r_in, c0, ks + 1, 1, bufB);

        uint32_t k2 = (uint32_t)ks * 32;
        #pragma unroll
        for (int q = 0; q < 4; q++) {
            uint32_t bh[4], bl[4];
            ldsm4(bh, Bhi + q * (16 * SPAD_B) + k2);
            ldsm4(bl, Blo + q * (16 * SPAD_B) + k2);
            #pragma unroll
            for (int mt = 0; mt < 2; mt++) {
                mma16816(acc[mt][q * 2],     ah[mt], bh);
                mma16816(acc[mt][q * 2],     ah[mt], bl);
                mma16816(acc[mt][q * 2],     al[mt], bh);
                mma16816(acc[mt][q * 2 + 1], ah[mt], bh + 2);
                mma16816(acc[mt][q * 2 + 1], ah[mt], bl + 2);
                mma16816(acc[mt][q * 2 + 1], al[mt], bh + 2);
            }
        }
    }
}

// ---------------- zero scratch ----------------
__global__ void zero_kernel(int n) {
    size_t idx = (size_t)blockIdx.x * blockDim.x + threadIdx.x;
    size_t stride = (size_t)gridDim.x * blockDim.x;
    float4 z = make_float4(0.f, 0.f, 0.f, 0.f);
    size_t nS = (size_t)T_TYPES * n * D / 4;
    for (size_t i = idx; i < nS; i += stride) reinterpret_cast<float4*>(g_S)[i] = z;
    size_t n2 = (size_t)n * D / 4;
    for (size_t i = idx; i < n2; i += stride) reinterpret_cast<float4*>(g_acc2)[i] = z;
    size_t nd = (size_t)T_TYPES * n;
    for (size_t i = idx; i < nd; i += stride) g_deg[i] = 0;
}

// ---------------- prep: weights -> bf16 hi/lo, Bt[n][k] = W[k][n] ----------------
__global__ void prep_kernel(const float* __restrict__ Wt, const float* __restrict__ W1,
                            const float* __restrict__ W2, const float* __restrict__ Ws) {
    int id = blockIdx.x * blockDim.x + threadIdx.x;
    if (id >= 7 * 128 * 128) return;
    int m = id >> 14;
    int e = id & 16383;
    int nrow = e >> 7;
    int k = e & 127;
    const float* W = (m < 4) ? (Wt + (size_t)m * 128 * 128)
                             : ((m == 4) ? W1 : ((m == 5) ? W2 : Ws));
    float v = W[k * 128 + nrow];
    __nv_bfloat16 hi = __float2bfloat16(v);
    __nv_bfloat16 lo = __float2bfloat16(v - __bfloat162float(hi));
    g_Whi[m][nrow * 128 + k] = hi;
    g_Wlo[m][nrow * 128 + k] = lo;
}

// ---------------- edge kernel: H=relu(EF@W1+b1) scatter; x gather->S_t scatter ----------------
__global__ void __launch_bounds__(256, 2) edge_kernel(const float* __restrict__ x,
                                                      const float* __restrict__ ef,
                                                      const float* __restrict__ b1,
                                                      const int* __restrict__ erow,
                                                      const int* __restrict__ ecol,
                                                      const int* __restrict__ etype,
                                                      int E, int n) {
    extern __shared__ char dsm[];
    __shared__ float s_b1[128];
    __shared__ int s_r[128], s_c[128], s_t[128];

    int tid = threadIdx.x, lane = tid & 31, wid = tid >> 5;
    int m0 = blockIdx.x * 128;
    uint32_t sb = smem_u32(dsm);

    if (tid < 128) {
        s_b1[tid] = b1[tid];
        int e = m0 + tid;
        if (e < E) {
            int r = erow[e], t = etype[e];
            s_r[tid] = r; s_c[tid] = ecol[e]; s_t[tid] = t;
            atomicAdd(&g_deg[(size_t)t * n + r], 1);
        }
    }
    copy_B(g_Whi[4], g_Wlo[4], dsm, tid);
    __syncthreads();

    float acc[2][8][4];
    #pragma unroll
    for (int mt = 0; mt < 2; mt++)
        #pragma unroll
        for (int nt = 0; nt < 8; nt++)
            #pragma unroll
            for (int j = 0; j < 4; j++) acc[mt][nt][j] = 0.f;

    int m0w = (wid >> 1) * 32, n0w = (wid & 1) * 64;
    warp_gemm_regA(ef, m0 + m0w, E, sb, lane, n0w, acc);

    // H epilogue: relu + bias -> red into g_acc2[row]
    #pragma unroll
    for (int mt = 0; mt < 2; mt++) {
        int er0 = m0w + mt * 16 + (lane >> 2);
        int er1 = er0 + 8;
        bool v0 = (m0 + er0) < E, v1 = (m0 + er1) < E;
        int r0 = v0 ? s_r[er0] : 0, r1 = v1 ? s_r[er1] : 0;
        #pragma unroll
        for (int nt = 0; nt < 8; nt++) {
            int cj = n0w + nt * 8 + (lane & 3) * 2;
            float bb0 = s_b1[cj], bb1 = s_b1[cj + 1];
            if (v0) {
                float h0 = fmaxf(acc[mt][nt][0] + bb0, 0.f);
                float h1 = fmaxf(acc[mt][nt][1] + bb1, 0.f);
                red_add_v2(g_acc2 + (size_t)r0 * D + cj, h0, h1);
            }
            if (v1) {
                float h2 = fmaxf(acc[mt][nt][2] + bb0, 0.f);
                float h3 = fmaxf(acc[mt][nt][3] + bb1, 0.f);
                red_add_v2(g_acc2 + (size_t)r1 * D + cj, h2, h3);
            }
        }
    }

    // x gather -> S_t scatter (2 threads per edge)
    {
        int el = tid >> 1;
        int half = (tid & 1) * 64;
        int e = m0 + el;
        if (e < E) {
            int r = s_r[el], cn = s_c[el], t = s_t[el];
            const float4* xs = reinterpret_cast<const float4*>(x + (size_t)cn * D + half);
            float* dst = g_S + ((size_t)t * n + r) * D + half;
            #pragma unroll
            for (int j = 0; j < 16; j++) red_add_v4(dst + 4 * j, xs[j]);
        }
    }
}

// ---------------- final: out = relu(LN(sum_t S_t@W_t + acc2@W2 + x@Wself + biases)) ------------
__global__ void __launch_bounds__(256, 2) final_kernel(const float* __restrict__ x,
                                                       const float* __restrict__ bself,
                                                       const float* __restrict__ btypes,
                                                       const float* __restrict__ be2,
                                                       const float* __restrict__ lng,
                                                       const float* __restrict__ lnb,
                                                       float* __restrict__ out,
                                                       int n) {
    extern __shared__ char dsm[];
    __shared__ float s_bself[128], s_be2[128], s_g[128], s_lb[128];
    __shared__ float s_bt[T_TYPES][128];

    int tid = threadIdx.x, lane = tid & 31, wid = tid >> 5;
    int m0 = blockIdx.x * 128;
    uint32_t sb = smem_u32(dsm);

    if (tid < 128) {
        s_bself[tid] = bself[tid];
        s_be2[tid] = be2[tid];
        s_g[tid] = lng[tid];
        s_lb[tid] = lnb[tid];
        #pragma unroll
        for (int t = 0; t < T_TYPES; t++) s_bt[t][tid] = btypes[t * D + tid];
    }

    float acc[2][8][4];
    #pragma unroll
    for (int mt = 0; mt < 2; mt++)
        #pragma unroll
        for (int nt = 0; nt < 8; nt++)
            #pragma unroll
            for (int j = 0; j < 4; j++) acc[mt][nt][j] = 0.f;

    int m0w = (wid >> 1) * 32, n0w = (wid & 1) * 64;

    #pragma unroll 1
    for (int ph = 0; ph < 6; ph++) {
        const float* srcA;
        int mat;
        if (ph < 4)      { srcA = g_S + (size_t)ph * n * D; mat = ph; }
        else if (ph == 4){ srcA = g_acc2;                   mat = 5;  }
        else             { srcA = x;                        mat = 6;  }
        __syncthreads();
        copy_B(g_Whi[mat], g_Wlo[mat], dsm, tid);
        __syncthreads();
        warp_gemm_regA(srcA, m0 + m0w, n, sb, lane, n0w, acc);
    }
    __syncthreads();   // all smem B reads done; safe to alias C over B region

    // stage C into smem f32 [128][C_STRIDE]
    float* Cs = reinterpret_cast<float*>(dsm);
    #pragma unroll
    for (int mt = 0; mt < 2; mt++) {
        int er0 = m0w + mt * 16 + (lane >> 2);
        #pragma unroll
        for (int nt = 0; nt < 8; nt++) {
            int cj = n0w + nt * 8 + (lane & 3) * 2;
            Cs[er0 * C_STRIDE + cj]       = acc[mt][nt][0];
            Cs[er0 * C_STRIDE + cj + 1]   = acc[mt][nt][1];
            Cs[(er0 + 8) * C_STRIDE + cj]     = acc[mt][nt][2];
            Cs[(er0 + 8) * C_STRIDE + cj + 1] = acc[mt][nt][3];
        }
    }
    __syncthreads();

    // per-row LN (threads 0..127)
    if (tid < 128) {
        int gm = m0 + tid;
        if (gm < n) {
            int d0 = g_deg[0 * (size_t)n + gm];
            int d1 = g_deg[1 * (size_t)n + gm];
            int d2 = g_deg[2 * (size_t)n + gm];
            int d3 = g_deg[3 * (size_t)n + gm];
            float f0 = (float)d0, f1 = (float)d1, f2 = (float)d2, f3 = (float)d3;
            float degs = f0 + f1 + f2 + f3;
            float* row = Cs + tid * C_STRIDE;
            float s = 0.f, sq = 0.f;
            #pragma unroll 8
            for (int j = 0; j < 128; j++) {
                float val = row[j] + s_bself[j]
                          + f0 * s_bt[0][j] + f1 * s_bt[1][j]
                          + f2 * s_bt[2][j] + f3 * s_bt[3][j]
                          + degs * s_be2[j];
                row[j] = val;
                s += val; sq += val * val;
            }
            float mu = s * (1.f / 128.f);
            float var = sq * (1.f / 128.f) - mu * mu;
            float inv = rsqrtf(fmaxf(var, 0.f) + EPS);
            float* op = out + (size_t)gm * D;
            #pragma unroll 8
            for (int j = 0; j < 32; j++) {
                float4 o;
                o.x = fmaxf((row[4*j+0] - mu) * inv * s_g[4*j+0] + s_lb[4*j+0], 0.f);
                o.y = fmaxf((row[4*j+1] - mu) * inv * s_g[4*j+1] + s_lb[4*j+1], 0.f);
                o.z = fmaxf((row[4*j+2] - mu) * inv * s_g[4*j+2] + s_lb[4*j+2], 0.f);
                o.w = fmaxf((row[4*j+3] - mu) * inv * s_g[4*j+3] + s_lb[4*j+3], 0.f);
                *reinterpret_cast<float4*>(op + 4 * j) = o;
            }
        }
    }
}

// ---------------- launch ----------------
extern "C" void kernel_launch(void* const* d_in, const int* in_sizes, int n_in,
                              void* d_out, int out_size) {
    const float* x    = (const float*)d_in[0];
    const int*   ei   = (const int*)d_in[1];
    const int*   etyp = (const int*)d_in[2];
    const float* ef   = (const float*)d_in[3];
    const float* Wt   = (const float*)d_in[4];
    const float* bt   = (const float*)d_in[5];
    const float* Ws   = (const float*)d_in[6];
    const float* bs   = (const float*)d_in[7];
    const float* W1   = (const float*)d_in[8];
    const float* b1   = (const float*)d_in[9];
    const float* W2   = (const float*)d_in[10];
    const float* b2   = (const float*)d_in[11];
    const float* lg   = (const float*)d_in[12];
    const float* lb   = (const float*)d_in[13];
    float* out = (float*)d_out;

    int E = in_sizes[2];
    int n = in_sizes[0] / D;
    const int* erow = ei;       // destinations (segment ids)
    const int* ecol = ei + E;   // sources (gather ids)

    cudaFuncSetAttribute(edge_kernel, cudaFuncAttributeMaxDynamicSharedMemorySize, DSMEM_BYTES);
    cudaFuncSetAttribute(final_kernel, cudaFuncAttributeMaxDynamicSharedMemorySize, DSMEM_BYTES);

    zero_kernel<<<1024, 256>>>(n);
    prep_kernel<<<(7 * 128 * 128 + 255) / 256, 256>>>(Wt, W1, W2, Ws);
    edge_kernel<<<(E + 127) / 128, 256, DSMEM_BYTES>>>(x, ef, b1, erow, ecol, etyp, E, n);
    final_kernel<<<(n + 127) / 128, 256, DSMEM_BYTES>>>(x, bs, bt, b2, lg, lb, out, n);
}

// round 15
// speedup vs baseline: 1.4949x; 1.0113x over previous
#include <cuda_runtime.h>
#include <cuda_bf16.h>
#include <cstdint>

#define D 128
#define T_TYPES 4
#define MAX_N 50000
#define MAX_E 500000
#define EPS 1e-5f

// smem: only B tiles (bf16 hi/lo), 272B row stride
#define SPAD_B 272
#define OFF_BHI 0
#define OFF_BLO 34816
#define DSMEM_BYTES 69632
// final kernel C-stage aliases B region: f32, row stride 133 words (68096B <= 69632)
#define C_STRIDE 133

typedef unsigned long long u64;

// ---------------- scratch ----------------
__device__ float g_S[(size_t)T_TYPES * MAX_N * D];   // per-type summed source features
__device__ float g_acc2[(size_t)MAX_N * D];          // scattered H = relu(EF@W1+b1)
__device__ int   g_deg[T_TYPES * MAX_N];
// preconverted weights bf16 hi/lo, layout Bt[n][k] = W[k][n]
// mats: 0..3 = W_types, 4 = W_e1, 5 = W_e2, 6 = W_self
__device__ __nv_bfloat16 g_Whi[7][128 * 128];
__device__ __nv_bfloat16 g_Wlo[7][128 * 128];

// ---------------- helpers ----------------
__device__ __forceinline__ void red_add_v4(float* addr, float4 v) {
    asm volatile("red.global.add.v4.f32 [%0], {%1, %2, %3, %4};"
                 :: "l"(addr), "f"(v.x), "f"(v.y), "f"(v.z), "f"(v.w) : "memory");
}
__device__ __forceinline__ void red_add_v2(float* addr, float a, float b) {
    asm volatile("red.global.add.v2.f32 [%0], {%1, %2};"
                 :: "l"(addr), "f"(a), "f"(b) : "memory");
}
__device__ __forceinline__ uint32_t smem_u32(const void* p) {
    uint32_t a;
    asm("{ .reg .u64 t; cvta.to.shared.u64 t, %1; cvt.u32.u64 %0, t; }" : "=r"(a) : "l"(p));
    return a;
}
__device__ __forceinline__ void ldsm4(uint32_t* r, uint32_t addr) {
    asm volatile("ldmatrix.sync.aligned.m8n8.x4.shared.b16 {%0,%1,%2,%3}, [%4];"
                 : "=r"(r[0]), "=r"(r[1]), "=r"(r[2]), "=r"(r[3]) : "r"(addr));
}
__device__ __forceinline__ void mma16816(float* c, const uint32_t* a, const uint32_t* b) {
    asm volatile("mma.sync.aligned.m16n8k16.row.col.f32.bf16.bf16.f32 "
                 "{%0,%1,%2,%3}, {%4,%5,%6,%7}, {%8,%9}, {%0,%1,%2,%3};"
                 : "+f"(c[0]), "+f"(c[1]), "+f"(c[2]), "+f"(c[3])
                 : "r"(a[0]), "r"(a[1]), "r"(a[2]), "r"(a[3]), "r"(b[0]), "r"(b[1]));
}
// truncation-based hi/lo split for a pair of floats -> two bf16x2 words.
// hi = top 16 bits of each float (PRMT); rem = x - hi (exact); lo = top 16 of rem.
__device__ __forceinline__ void cvt_hilo2(float x, float y, uint32_t& hi, uint32_t& lo) {
    uint32_t ux = __float_as_uint(x), uy = __float_as_uint(y);
    hi = __byte_perm(ux, uy, 0x7632);
    float rx = x - __uint_as_float(ux & 0xFFFF0000u);
    float ry = y - __uint_as_float(uy & 0xFFFF0000u);
    lo = __byte_perm(__float_as_uint(rx), __float_as_uint(ry), 0x7632);
}
// convert one A fragment (4 x float2) into mma-ordered bf16x2 regs
__device__ __forceinline__ void cvt_frag(const float2 v[4], uint32_t ah[4], uint32_t al[4]) {
    cvt_hilo2(v[0].x, v[0].y, ah[0], al[0]);
    cvt_hilo2(v[2].x, v[2].y, ah[1], al[1]);
    cvt_hilo2(v[1].x, v[1].y, ah[2], al[2]);
    cvt_hilo2(v[3].x, v[3].y, ah[3], al[3]);
}

// copy preconverted B tile ([n][k] bf16) into padded smem
__device__ __forceinline__ void copy_B(const __nv_bfloat16* ghi, const __nv_bfloat16* glo,
                                       char* dsm, int tid) {
    const uint4* sh = reinterpret_cast<const uint4*>(ghi);
    const uint4* sl = reinterpret_cast<const uint4*>(glo);
    #pragma unroll 4
    for (int it = 0; it < 8; it++) {
        int idx = it * 256 + tid;           // 2048 uint4 chunks
        int row = idx >> 4;
        int cb = (idx & 15) * 16;
        *reinterpret_cast<uint4*>(dsm + OFF_BHI + row * SPAD_B + cb) = sh[idx];
        *reinterpret_cast<uint4*>(dsm + OFF_BLO + row * SPAD_B + cb) = sl[idx];
    }
}

// load one A fragment pair (4 x float2) for (ks, mt)
__device__ __forceinline__ void loadA_pair(const float* __restrict__ srcA, int gr_base,
                                           int limit, int r_in, int c0, int ks, int mt,
                                           float2 v[4]) {
    int ra = gr_base + mt * 16 + r_in;
    int rb = ra + 8;
    int col = ks * 16 + c0;
    const float* pa = srcA + (size_t)ra * D + col;
    const float* pb = srcA + (size_t)rb * D + col;
    float2 z2 = make_float2(0.f, 0.f);
    v[0] = (ra < limit) ? *reinterpret_cast<const float2*>(pa)     : z2;
    v[1] = (ra < limit) ? *reinterpret_cast<const float2*>(pa + 8) : z2;
    v[2] = (rb < limit) ? *reinterpret_cast<const float2*>(pb)     : z2;
    v[3] = (rb < limit) ? *reinterpret_cast<const float2*>(pb + 8) : z2;
}

// warp GEMM, A from GLOBAL with one-ks-ahead register prefetch (two buffers).
// C[tile] += A * Bt^T, split-bf16 3-product, K=128, warp tile m32 x n64.
// MMA stream ordered for same-accumulator distance 4 (q-pair grouping).
__device__ __forceinline__ void warp_gemm_regA(const float* __restrict__ srcA,
                                               int gr_base, int limit,
                                               uint32_t sb, int lane, int n0w,
                                               float acc[2][8][4]) {
    int r_in = lane >> 2;
    int c0 = (lane & 3) * 2;
    uint32_t boff = (uint32_t)((n0w + (lane & 7) + ((lane >> 3) & 2) * 4) * SPAD_B
                               + ((lane >> 3) & 1) * 16);
    uint32_t Bhi = sb + OFF_BHI + boff, Blo = sb + OFF_BLO + boff;

    float2 bufA[4], bufB[4];
    loadA_pair(srcA, gr_base, limit, r_in, c0, 0, 0, bufA);
    loadA_pair(srcA, gr_base, limit, r_in, c0, 0, 1, bufB);

    #pragma unroll
    for (int ks = 0; ks < 8; ks++) {
        uint32_t ah[2][4], al[2][4];
        cvt_frag(bufA, ah[0], al[0]);
        if (ks < 7) loadA_pair(srcA, gr_base, limit, r_in, c0, ks + 1, 0, bufA);
        cvt_frag(bufB, ah[1], al[1]);
        if (ks < 7) loadA_pair(srcA, gr_base, limit, r_in, c0, ks + 1, 1, bufB);

        uint32_t k2 = (uint32_t)ks * 32;
        #pragma unroll
        for (int qp = 0; qp < 2; qp++) {
            uint32_t bh0[4], bl0[4], bh1[4], bl1[4];
            ldsm4(bh0, Bhi + (2 * qp)     * (16 * SPAD_B) + k2);
            ldsm4(bl0, Blo + (2 * qp)     * (16 * SPAD_B) + k2);
            ldsm4(bh1, Bhi + (2 * qp + 1) * (16 * SPAD_B) + k2);
            ldsm4(bl1, Blo + (2 * qp + 1) * (16 * SPAD_B) + k2);
            #pragma unroll
            for (int mt = 0; mt < 2; mt++) {
                float* c0p = acc[mt][qp * 4 + 0];
                float* c1p = acc[mt][qp * 4 + 1];
                float* c2p = acc[mt][qp * 4 + 2];
                float* c3p = acc[mt][qp * 4 + 3];
                // product hi*hi
                mma16816(c0p, ah[mt], bh0);
                mma16816(c1p, ah[mt], bh0 + 2);
                mma16816(c2p, ah[mt], bh1);
                mma16816(c3p, ah[mt], bh1 + 2);
                // product hi*lo
                mma16816(c0p, ah[mt], bl0);
                mma16816(c1p, ah[mt], bl0 + 2);
                mma16816(c2p, ah[mt], bl1);
                mma16816(c3p, ah[mt], bl1 + 2);
                // product lo*hi
                mma16816(c0p, al[mt], bh0);
                mma16816(c1p, al[mt], bh0 + 2);
                mma16816(c2p, al[mt], bh1);
                mma16816(c3p, al[mt], bh1 + 2);
            }
        }
    }
}

// ---------------- zero scratch ----------------
__global__ void zero_kernel(int n) {
    size_t idx = (size_t)blockIdx.x * blockDim.x + threadIdx.x;
    size_t stride = (size_t)gridDim.x * blockDim.x;
    float4 z = make_float4(0.f, 0.f, 0.f, 0.f);
    size_t nS = (size_t)T_TYPES * n * D / 4;
    for (size_t i = idx; i < nS; i += stride) reinterpret_cast<float4*>(g_S)[i] = z;
    size_t n2 = (size_t)n * D / 4;
    for (size_t i = idx; i < n2; i += stride) reinterpret_cast<float4*>(g_acc2)[i] = z;
    size_t nd = (size_t)T_TYPES * n;
    for (size_t i = idx; i < nd; i += stride) g_deg[i] = 0;
}

// ---------------- prep: weights -> bf16 hi/lo, Bt[n][k] = W[k][n] ----------------
__global__ void prep_kernel(const float* __restrict__ Wt, const float* __restrict__ W1,
                            const float* __restrict__ W2, const float* __restrict__ Ws) {
    int id = blockIdx.x * blockDim.x + threadIdx.x;
    if (id >= 7 * 128 * 128) return;
    int m = id >> 14;
    int e = id & 16383;
    int nrow = e >> 7;
    int k = e & 127;
    const float* W = (m < 4) ? (Wt + (size_t)m * 128 * 128)
                             : ((m == 4) ? W1 : ((m == 5) ? W2 : Ws));
    float v = W[k * 128 + nrow];
    __nv_bfloat16 hi = __float2bfloat16(v);
    __nv_bfloat16 lo = __float2bfloat16(v - __bfloat162float(hi));
    g_Whi[m][nrow * 128 + k] = hi;
    g_Wlo[m][nrow * 128 + k] = lo;
}

// ---------------- edge kernel: H=relu(EF@W1+b1) scatter; x gather->S_t scatter ----------------
__global__ void __launch_bounds__(256, 2) edge_kernel(const float* __restrict__ x,
                                                      const float* __restrict__ ef,
                                                      const float* __restrict__ b1,
                                                      const int* __restrict__ erow,
                                                      const int* __restrict__ ecol,
                                                      const int* __restrict__ etype,
                                                      int E, int n) {
    extern __shared__ char dsm[];
    __shared__ float s_b1[128];
    __shared__ int s_r[128], s_c[128], s_t[128];

    int tid = threadIdx.x, lane = tid & 31, wid = tid >> 5;
    int m0 = blockIdx.x * 128;
    uint32_t sb = smem_u32(dsm);

    if (tid < 128) {
        s_b1[tid] = b1[tid];
        int e = m0 + tid;
        if (e < E) {
            int r = erow[e], t = etype[e];
            s_r[tid] = r; s_c[tid] = ecol[e]; s_t[tid] = t;
            atomicAdd(&g_deg[(size_t)t * n + r], 1);
        }
    }
    copy_B(g_Whi[4], g_Wlo[4], dsm, tid);
    __syncthreads();

    float acc[2][8][4];
    #pragma unroll
    for (int mt = 0; mt < 2; mt++)
        #pragma unroll
        for (int nt = 0; nt < 8; nt++)
            #pragma unroll
            for (int j = 0; j < 4; j++) acc[mt][nt][j] = 0.f;

    int m0w = (wid >> 1) * 32, n0w = (wid & 1) * 64;
    warp_gemm_regA(ef, m0 + m0w, E, sb, lane, n0w, acc);

    // H epilogue: relu + bias -> red into g_acc2[row]
    #pragma unroll
    for (int mt = 0; mt < 2; mt++) {
        int er0 = m0w + mt * 16 + (lane >> 2);
        int er1 = er0 + 8;
        bool v0 = (m0 + er0) < E, v1 = (m0 + er1) < E;
        int r0 = v0 ? s_r[er0] : 0, r1 = v1 ? s_r[er1] : 0;
        #pragma unroll
        for (int nt = 0; nt < 8; nt++) {
            int cj = n0w + nt * 8 + (lane & 3) * 2;
            float bb0 = s_b1[cj], bb1 = s_b1[cj + 1];
            if (v0) {
                float h0 = fmaxf(acc[mt][nt][0] + bb0, 0.f);
                float h1 = fmaxf(acc[mt][nt][1] + bb1, 0.f);
                red_add_v2(g_acc2 + (size_t)r0 * D + cj, h0, h1);
            }
            if (v1) {
                float h2 = fmaxf(acc[mt][nt][2] + bb0, 0.f);
                float h3 = fmaxf(acc[mt][nt][3] + bb1, 0.f);
                red_add_v2(g_acc2 + (size_t)r1 * D + cj, h2, h3);
            }
        }
    }

    // x gather -> S_t scatter (2 threads per edge)
    {
        int el = tid >> 1;
        int half = (tid & 1) * 64;
        int e = m0 + el;
        if (e < E) {
            int r = s_r[el], cn = s_c[el], t = s_t[el];
            const float4* xs = reinterpret_cast<const float4*>(x + (size_t)cn * D + half);
            float* dst = g_S + ((size_t)t * n + r) * D + half;
            #pragma unroll
            for (int j = 0; j < 16; j++) red_add_v4(dst + 4 * j, xs[j]);
        }
    }
}

// ---------------- final: out = relu(LN(sum_t S_t@W_t + acc2@W2 + x@Wself + biases)) ------------
__global__ void __launch_bounds__(256, 2) final_kernel(const float* __restrict__ x,
                                                       const float* __restrict__ bself,
                                                       const float* __restrict__ btypes,
                                                       const float* __restrict__ be2,
                                                       const float* __restrict__ lng,
                                                       const float* __restrict__ lnb,
                                                       float* __restrict__ out,
                                                       int n) {
    extern __shared__ char dsm[];
    __shared__ float s_bself[128], s_be2[128], s_g[128], s_lb[128];
    __shared__ float s_bt[T_TYPES][128];

    int tid = threadIdx.x, lane = tid & 31, wid = tid >> 5;
    int m0 = blockIdx.x * 128;
    uint32_t sb = smem_u32(dsm);

    if (tid < 128) {
        s_bself[tid] = bself[tid];
        s_be2[tid] = be2[tid];
        s_g[tid] = lng[tid];
        s_lb[tid] = lnb[tid];
        #pragma unroll
        for (int t = 0; t < T_TYPES; t++) s_bt[t][tid] = btypes[t * D + tid];
    }

    float acc[2][8][4];
    #pragma unroll
    for (int mt = 0; mt < 2; mt++)
        #pragma unroll
        for (int nt = 0; nt < 8; nt++)
            #pragma unroll
            for (int j = 0; j < 4; j++) acc[mt][nt][j] = 0.f;

    int m0w = (wid >> 1) * 32, n0w = (wid & 1) * 64;

    #pragma unroll 1
    for (int ph = 0; ph < 6; ph++) {
        const float* srcA;
        int mat;
        if (ph < 4)      { srcA = g_S + (size_t)ph * n * D; mat = ph; }
        else if (ph == 4){ srcA = g_acc2;                   mat = 5;  }
        else             { srcA = x;                        mat = 6;  }
        __syncthreads();
        copy_B(g_Whi[mat], g_Wlo[mat], dsm, tid);
        __syncthreads();
        warp_gemm_regA(srcA, m0 + m0w, n, sb, lane, n0w, acc);
    }
    __syncthreads();   // all smem B reads done; safe to alias C over B region

    // stage C into smem f32 [128][C_STRIDE]
    float* Cs = reinterpret_cast<float*>(dsm);
    #pragma unroll
    for (int mt = 0; mt < 2; mt++) {
        int er0 = m0w + mt * 16 + (lane >> 2);
        #pragma unroll
        for (int nt = 0; nt < 8; nt++) {
            int cj = n0w + nt * 8 + (lane & 3) * 2;
            Cs[er0 * C_STRIDE + cj]       = acc[mt][nt][0];
            Cs[er0 * C_STRIDE + cj + 1]   = acc[mt][nt][1];
            Cs[(er0 + 8) * C_STRIDE + cj]     = acc[mt][nt][2];
            Cs[(er0 + 8) * C_STRIDE + cj + 1] = acc[mt][nt][3];
        }
    }
    __syncthreads();

    // per-row LN (threads 0..127)
    if (tid < 128) {
        int gm = m0 + tid;
        if (gm < n) {
            int d0 = g_deg[0 * (size_t)n + gm];
            int d1 = g_deg[1 * (size_t)n + gm];
            int d2 = g_deg[2 * (size_t)n + gm];
            int d3 = g_deg[3 * (size_t)n + gm];
            float f0 = (float)d0, f1 = (float)d1, f2 = (float)d2, f3 = (float)d3;
            float degs = f0 + f1 + f2 + f3;
            float* row = Cs + tid * C_STRIDE;
            float s = 0.f, sq = 0.f;
            #pragma unroll 8
            for (int j = 0; j < 128; j++) {
                float val = row[j] + s_bself[j]
                          + f0 * s_bt[0][j] + f1 * s_bt[1][j]
                          + f2 * s_bt[2][j] + f3 * s_bt[3][j]
                          + degs * s_be2[j];
                row[j] = val;
                s += val; sq += val * val;
            }
            float mu = s * (1.f / 128.f);
            float var = sq * (1.f / 128.f) - mu * mu;
            float inv = rsqrtf(fmaxf(var, 0.f) + EPS);
            float* op = out + (size_t)gm * D;
            #pragma unroll 8
            for (int j = 0; j < 32; j++) {
                float4 o;
                o.x = fmaxf((row[4*j+0] - mu) * inv * s_g[4*j+0] + s_lb[4*j+0], 0.f);
                o.y = fmaxf((row[4*j+1] - mu) * inv * s_g[4*j+1] + s_lb[4*j+1], 0.f);
                o.z = fmaxf((row[4*j+2] - mu) * inv * s_g[4*j+2] + s_lb[4*j+2], 0.f);
                o.w = fmaxf((row[4*j+3] - mu) * inv * s_g[4*j+3] + s_lb[4*j+3], 0.f);
                *reinterpret_cast<float4*>(op + 4 * j) = o;
            }
        }
    }
}

// ---------------- launch ----------------
extern "C" void kernel_launch(void* const* d_in, const int* in_sizes, int n_in,
                              void* d_out, int out_size) {
    const float* x    = (const float*)d_in[0];
    const int*   ei   = (const int*)d_in[1];
    const int*   etyp = (const int*)d_in[2];
    const float* ef   = (const float*)d_in[3];
    const float* Wt   = (const float*)d_in[4];
    const float* bt   = (const float*)d_in[5];
    const float* Ws   = (const float*)d_in[6];
    const float* bs   = (const float*)d_in[7];
    const float* W1   = (const float*)d_in[8];
    const float* b1   = (const float*)d_in[9];
    const float* W2   = (const float*)d_in[10];
    const float* b2   = (const float*)d_in[11];
    const float* lg   = (const float*)d_in[12];
    const float* lb   = (const float*)d_in[13];
    float* out = (float*)d_out;

    int E = in_sizes[2];
    int n = in_sizes[0] / D;
    const int* erow = ei;       // destinations (segment ids)
    const int* ecol = ei + E;   // sources (gather ids)

    cudaFuncSetAttribute(edge_kernel, cudaFuncAttributeMaxDynamicSharedMemorySize, DSMEM_BYTES);
    cudaFuncSetAttribute(final_kernel, cudaFuncAttributeMaxDynamicSharedMemorySize, DSMEM_BYTES);

    zero_kernel<<<1024, 256>>>(n);
    prep_kernel<<<(7 * 128 * 128 + 255) / 256, 256>>>(Wt, W1, W2, Ws);
    edge_kernel<<<(E + 127) / 128, 256, DSMEM_BYTES>>>(x, ef, b1, erow, ecol, etyp, E, n);
    final_kernel<<<(n + 127) / 128, 256, DSMEM_BYTES>>>(x, bs, bt, b2, lg, lb, out, n);
}